// round 3
// baseline (speedup 1.0000x reference)
#include <cuda_runtime.h>

#define EPS 1e-5f

typedef unsigned long long u64;

union f2u { u64 u; float2 f; };

__device__ __forceinline__ u64 pack2(float lo, float hi) {
    u64 r; asm("mov.b64 %0, {%1,%2};" : "=l"(r) : "f"(lo), "f"(hi)); return r;
}
__device__ __forceinline__ void ffma2(u64 &d, u64 a, u64 b) {
    asm("fma.rn.f32x2 %0, %1, %2, %0;" : "+l"(d) : "l"(a), "l"(b));
}

// Scratch: qkv[n=8][o=256][h=128][w=128] fp32 = 128 MB
__device__ float g_qkv[33554432];
// W transposed: [c=128][o=256] = 128 KB
__device__ float g_wt[32768];

// ---------------- Kernel 0: transpose W (tiny) ----------------
__global__ void wt_kernel(const float* __restrict__ w) {
    int idx = blockIdx.x * 256 + threadIdx.x;   // 0..32767
    int o = idx >> 7, c = idx & 127;
    g_wt[c * 256 + o] = w[idx];
}

// ---------------- Kernel 1: QKV GEMM + BN ----------------
// Y[n][o][p] = sum_c W[o][c] * x[n][c][p]. Block: 128o x 128p, K chunk 64.
// Thread tile: 8o x 8p (f32x2).
__global__ __launch_bounds__(256) void qkv_kernel(
    const float* __restrict__ x,
    const float* __restrict__ qg, const float* __restrict__ qb,
    const float* __restrict__ qm, const float* __restrict__ qv) {
    __shared__ float xs[64][128];   // [c][p]
    __shared__ float ws[64][128];   // [c][o]
    int tid = threadIdx.x;
    int pt = blockIdx.x, ot = blockIdx.y, n = blockIdx.z;
    const float* xp = x + (size_t)n * (128 * 16384) + pt * 128;
    int ob = (tid >> 4) * 8;
    int pb = (tid & 15) * 8;

    f2u acc[8][4];
#pragma unroll
    for (int a = 0; a < 8; a++)
#pragma unroll
        for (int b = 0; b < 4; b++) acc[a][b].u = 0ull;

    for (int cc = 0; cc < 2; cc++) {
        // xs: 64c x 128p, float4 coalesced
#pragma unroll
        for (int k = 0; k < 8; k++) {
            int f = tid + k * 256;
            int c = f >> 5, p4 = (f & 31) << 2;
            *(float4*)&xs[c][p4] =
                *(const float4*)(xp + (size_t)(cc * 64 + c) * 16384 + p4);
        }
        // ws: 64c x 128o from pre-transposed g_wt, float4 coalesced, no conflicts
#pragma unroll
        for (int k = 0; k < 8; k++) {
            int f = tid + k * 256;
            int c = f >> 5, o4 = (f & 31) << 2;
            *(float4*)&ws[c][o4] =
                *(const float4*)(g_wt + (cc * 64 + c) * 256 + ot * 128 + o4);
        }
        __syncthreads();
#pragma unroll 4
        for (int c = 0; c < 64; c++) {
            float4 x0 = *(float4*)&xs[c][pb];
            float4 x1 = *(float4*)&xs[c][pb + 4];
            u64 b0 = pack2(x0.x, x0.y), b1 = pack2(x0.z, x0.w);
            u64 b2 = pack2(x1.x, x1.y), b3 = pack2(x1.z, x1.w);
            float4 w0 = *(float4*)&ws[c][ob];
            float4 w1 = *(float4*)&ws[c][ob + 4];
            u64 a0 = pack2(w0.x, w0.x), a1 = pack2(w0.y, w0.y);
            u64 a2 = pack2(w0.z, w0.z), a3 = pack2(w0.w, w0.w);
            u64 a4 = pack2(w1.x, w1.x), a5 = pack2(w1.y, w1.y);
            u64 a6 = pack2(w1.z, w1.z), a7 = pack2(w1.w, w1.w);
            ffma2(acc[0][0].u, a0, b0); ffma2(acc[0][1].u, a0, b1);
            ffma2(acc[0][2].u, a0, b2); ffma2(acc[0][3].u, a0, b3);
            ffma2(acc[1][0].u, a1, b0); ffma2(acc[1][1].u, a1, b1);
            ffma2(acc[1][2].u, a1, b2); ffma2(acc[1][3].u, a1, b3);
            ffma2(acc[2][0].u, a2, b0); ffma2(acc[2][1].u, a2, b1);
            ffma2(acc[2][2].u, a2, b2); ffma2(acc[2][3].u, a2, b3);
            ffma2(acc[3][0].u, a3, b0); ffma2(acc[3][1].u, a3, b1);
            ffma2(acc[3][2].u, a3, b2); ffma2(acc[3][3].u, a3, b3);
            ffma2(acc[4][0].u, a4, b0); ffma2(acc[4][1].u, a4, b1);
            ffma2(acc[4][2].u, a4, b2); ffma2(acc[4][3].u, a4, b3);
            ffma2(acc[5][0].u, a5, b0); ffma2(acc[5][1].u, a5, b1);
            ffma2(acc[5][2].u, a5, b2); ffma2(acc[5][3].u, a5, b3);
            ffma2(acc[6][0].u, a6, b0); ffma2(acc[6][1].u, a6, b1);
            ffma2(acc[6][2].u, a6, b2); ffma2(acc[6][3].u, a6, b3);
            ffma2(acc[7][0].u, a7, b0); ffma2(acc[7][1].u, a7, b1);
            ffma2(acc[7][2].u, a7, b2); ffma2(acc[7][3].u, a7, b3);
        }
        __syncthreads();
    }
#pragma unroll
    for (int oo = 0; oo < 8; oo++) {
        int o = ot * 128 + ob + oo;
        float s = qg[o] * rsqrtf(qv[o] + EPS);
        float t = qb[o] - qm[o] * s;
        float4 r0, r1;
        r0.x = acc[oo][0].f.x * s + t; r0.y = acc[oo][0].f.y * s + t;
        r0.z = acc[oo][1].f.x * s + t; r0.w = acc[oo][1].f.y * s + t;
        r1.x = acc[oo][2].f.x * s + t; r1.y = acc[oo][2].f.y * s + t;
        r1.z = acc[oo][3].f.x * s + t; r1.w = acc[oo][3].f.y * s + t;
        float* d = g_qkv + (size_t)(n * 256 + o) * 16384 + pt * 128 + pb;
        *(float4*)d = r0;
        *(float4*)(d + 4) = r1;
    }
}

// ---------------- Kernel 2: attention per (n, g, 4-wide w tile) ----------------
// 256 threads: thread = (q = j-quarter, i in 0..63) owning rows {i, i+64}.
// smem (floats):
//   qkv_t [4w][32ch][128h] : 0     .. 16384
//   ostage[16c][128h][4w]  : 16384 .. 24576
//   obuf  [3][16c][128h]   : 24576 .. 30720
//   redm  [4][128]         : 30720 .. 31232
//   reds  [4][128]         : 31232 .. 31744
//   osc[16], osh[16]       : 31744 .. 31776
#define SMEM2 (31776 * 4)

__global__ __launch_bounds__(256) void attn_kernel(
    const float* __restrict__ simg, const float* __restrict__ simv,
    const float* __restrict__ og, const float* __restrict__ obt,
    const float* __restrict__ om, const float* __restrict__ ov,
    float* __restrict__ out) {
    extern __shared__ float sm2[];
    float* qkv_t  = sm2;
    float* ostage = sm2 + 16384;
    float* obuf   = sm2 + 24576;
    float* redm   = sm2 + 30720;
    float* reds   = sm2 + 31232;
    float* osc    = sm2 + 31744;
    float* osh    = sm2 + 31760;

    int tid = threadIdx.x;
    int w0 = blockIdx.x * 4;
    int g  = blockIdx.y;
    int n  = blockIdx.z;

    const float* src = g_qkv + (size_t)(n * 256 + g * 32) * 16384 + w0;
#pragma unroll
    for (int k = 0; k < 16; k++) {
        int f = tid + k * 256;
        int h = f & 127;
        int ch = f >> 7;
        float4 v4 = *(const float4*)(src + (size_t)ch * 16384 + h * 128);
        qkv_t[(0 * 32 + ch) * 128 + h] = v4.x;
        qkv_t[(1 * 32 + ch) * 128 + h] = v4.y;
        qkv_t[(2 * 32 + ch) * 128 + h] = v4.z;
        qkv_t[(3 * 32 + ch) * 128 + h] = v4.w;
    }
    if (tid < 16) {
        int co = g * 16 + tid;
        float s = og[co] * rsqrtf(ov[co] + EPS);
        osc[tid] = s;
        osh[tid] = obt[co] - om[co] * s;
    }
    // sim BN shift cancels in softmax; only (positive) scale matters.
    float simscale = simg[g] * rsqrtf(simv[g] + EPS);
    __syncthreads();

    int q = tid >> 6;        // j quarter
    int i = tid & 63;        // row pair base: rows i, i+64
    int j0 = q * 32;

#pragma unroll 1
    for (int ww = 0; ww < 4; ww++) {
        const float* Q = qkv_t + ww * 32 * 128;
        u64 qd[2][8];
#pragma unroll
        for (int r = 0; r < 2; r++)
#pragma unroll
            for (int c = 0; c < 8; c++) {
                float v = Q[c * 128 + i + r * 64] * simscale;
                qd[r][c] = pack2(v, v);
            }
        f2u s2[2][16];
#pragma unroll
        for (int r = 0; r < 2; r++)
#pragma unroll
            for (int k = 0; k < 16; k++) s2[r][k].u = 0ull;
#pragma unroll
        for (int jj = 0; jj < 32; jj += 4) {
#pragma unroll
            for (int c = 0; c < 8; c++) {
                float4 k4 = *(const float4*)(Q + (8 + c) * 128 + j0 + jj);
                u64 kb0 = pack2(k4.x, k4.y);
                u64 kb1 = pack2(k4.z, k4.w);
                ffma2(s2[0][jj / 2].u,     qd[0][c], kb0);
                ffma2(s2[0][jj / 2 + 1].u, qd[0][c], kb1);
                ffma2(s2[1][jj / 2].u,     qd[1][c], kb0);
                ffma2(s2[1][jj / 2 + 1].u, qd[1][c], kb1);
            }
        }
        // softmax across the 4 quarters, 2 rows per thread
        float mx0 = -1e30f, mx1 = -1e30f;
#pragma unroll
        for (int k = 0; k < 16; k++) {
            mx0 = fmaxf(mx0, fmaxf(s2[0][k].f.x, s2[0][k].f.y));
            mx1 = fmaxf(mx1, fmaxf(s2[1][k].f.x, s2[1][k].f.y));
        }
        redm[q * 128 + i] = mx0;
        redm[q * 128 + i + 64] = mx1;
        __syncthreads();
        mx0 = fmaxf(fmaxf(redm[i], redm[128 + i]),
                    fmaxf(redm[256 + i], redm[384 + i]));
        mx1 = fmaxf(fmaxf(redm[i + 64], redm[128 + i + 64]),
                    fmaxf(redm[256 + i + 64], redm[384 + i + 64]));
        float sum0 = 0.f, sum1 = 0.f;
#pragma unroll
        for (int k = 0; k < 16; k++) {
            float e0 = __expf(s2[0][k].f.x - mx0);
            float e1 = __expf(s2[0][k].f.y - mx0);
            s2[0][k].f.x = e0; s2[0][k].f.y = e1;
            sum0 += e0 + e1;
            float f0 = __expf(s2[1][k].f.x - mx1);
            float f1 = __expf(s2[1][k].f.y - mx1);
            s2[1][k].f.x = f0; s2[1][k].f.y = f1;
            sum1 += f0 + f1;
        }
        reds[q * 128 + i] = sum0;
        reds[q * 128 + i + 64] = sum1;
        __syncthreads();
        float inv0 = 1.f / (reds[i] + reds[128 + i] + reds[256 + i] + reds[384 + i]);
        float inv1 = 1.f / (reds[i + 64] + reds[128 + i + 64] +
                            reds[256 + i + 64] + reds[384 + i + 64]);
        // O partials over this thread's j quarter, 2 rows
        f2u oc[2][16];
#pragma unroll
        for (int r = 0; r < 2; r++)
#pragma unroll
            for (int c = 0; c < 16; c++) oc[r][c].u = 0ull;
#pragma unroll
        for (int jj = 0; jj < 32; jj += 4) {
            u64 e00 = s2[0][jj / 2].u, e01 = s2[0][jj / 2 + 1].u;
            u64 e10 = s2[1][jj / 2].u, e11 = s2[1][jj / 2 + 1].u;
#pragma unroll
            for (int c = 0; c < 16; c++) {
                float4 v4 = *(const float4*)(Q + (16 + c) * 128 + j0 + jj);
                u64 vb0 = pack2(v4.x, v4.y);
                u64 vb1 = pack2(v4.z, v4.w);
                ffma2(oc[0][c].u, e00, vb0);
                ffma2(oc[0][c].u, e01, vb1);
                ffma2(oc[1][c].u, e10, vb0);
                ffma2(oc[1][c].u, e11, vb1);
            }
        }
        if (q) {
#pragma unroll
            for (int r = 0; r < 2; r++)
#pragma unroll
                for (int c = 0; c < 16; c++)
                    obuf[((q - 1) * 16 + c) * 128 + i + r * 64] =
                        oc[r][c].f.x + oc[r][c].f.y;
        }
        __syncthreads();
        if (!q) {
#pragma unroll
            for (int r = 0; r < 2; r++) {
                float inv = r ? inv1 : inv0;
                int row = i + r * 64;
#pragma unroll
                for (int c = 0; c < 16; c++) {
                    float t = (oc[r][c].f.x + oc[r][c].f.y
                               + obuf[c * 128 + row]
                               + obuf[(16 + c) * 128 + row]
                               + obuf[(32 + c) * 128 + row]) * inv;
                    ostage[(c * 128 + row) * 4 + ww] = t * osc[c] + osh[c];
                }
            }
        }
        __syncthreads();
    }
    // cooperative write-out: 4 contiguous w per (c, h) row
    float* dst = out + (size_t)(n * 128 + g * 16) * 16384 + w0;
#pragma unroll
    for (int k = 0; k < 8; k++) {
        int f = tid + k * 256;
        int c = f >> 7, h = f & 127;
        float4 a = *(float4*)&ostage[(c * 128 + h) * 4];
        *(float4*)(dst + (size_t)c * 16384 + h * 128) = a;
    }
}

extern "C" void kernel_launch(void* const* d_in, const int* in_sizes, int n_in,
                              void* d_out, int out_size) {
    const float* x    = (const float*)d_in[0];
    const float* wq   = (const float*)d_in[1];
    const float* qg   = (const float*)d_in[2];
    const float* qb   = (const float*)d_in[3];
    const float* qm   = (const float*)d_in[4];
    const float* qv   = (const float*)d_in[5];
    const float* simg = (const float*)d_in[6];
    // d_in[7] sim_beta, d_in[8] sim_mean: shift cancels in softmax
    const float* simv = (const float*)d_in[9];
    const float* og   = (const float*)d_in[10];
    const float* obt  = (const float*)d_in[11];
    const float* om   = (const float*)d_in[12];
    const float* ov   = (const float*)d_in[13];
    float* out = (float*)d_out;

    cudaFuncSetAttribute(attn_kernel,
                         cudaFuncAttributeMaxDynamicSharedMemorySize, SMEM2);

    wt_kernel<<<128, 256>>>(wq);
    qkv_kernel<<<dim3(128, 2, 8), 256>>>(x, qg, qb, qm, qv);
    attn_kernel<<<dim3(32, 8, 8), 256, SMEM2>>>(simg, simv, og, obt, om, ov, out);
}

// round 4
// speedup vs baseline: 1.0609x; 1.0609x over previous
#include <cuda_runtime.h>

#define EPS 1e-5f

typedef unsigned long long u64;
typedef unsigned int u32;

union f2u { u64 u; float2 f; };

__device__ __forceinline__ u64 pack2(float lo, float hi) {
    u64 r; asm("mov.b64 %0, {%1,%2};" : "=l"(r) : "f"(lo), "f"(hi)); return r;
}
__device__ __forceinline__ void ffma2(u64 &d, u64 a, u64 b) {
    asm("fma.rn.f32x2 %0, %1, %2, %0;" : "+l"(d) : "l"(a), "l"(b));
}
__device__ __forceinline__ u32 to_tf32(float v) {
    u32 r; asm("cvt.rna.tf32.f32 %0, %1;" : "=r"(r) : "f"(v)); return r;
}
__device__ __forceinline__ void mma_tf32(float* d, const u32* a, const u32* b) {
    asm volatile(
        "mma.sync.aligned.m16n8k8.row.col.f32.tf32.tf32.f32 "
        "{%0,%1,%2,%3}, {%4,%5,%6,%7}, {%8,%9}, {%0,%1,%2,%3};\n"
        : "+f"(d[0]), "+f"(d[1]), "+f"(d[2]), "+f"(d[3])
        : "r"(a[0]), "r"(a[1]), "r"(a[2]), "r"(a[3]), "r"(b[0]), "r"(b[1]));
}

// Scratch: qkv[n=8][o=256][h=128][w=128] fp32 = 128 MB
__device__ float g_qkv[33554432];
// W transposed+split: [c=128][o=256] hi / lo
__device__ float g_wt_hi[32768];
__device__ float g_wt_lo[32768];

// ---------------- Kernel 0: transpose + tf32-split W ----------------
__global__ void wt_kernel(const float* __restrict__ w) {
    int idx = blockIdx.x * 256 + threadIdx.x;   // 0..32767
    int o = idx >> 7, c = idx & 127;
    float v = w[idx];
    u32 h = to_tf32(v);
    float hf = __uint_as_float(h);
    u32 l = to_tf32(v - hf);
    g_wt_hi[c * 256 + o] = hf;
    g_wt_lo[c * 256 + o] = __uint_as_float(l);
}

// ---------------- Kernel 1: QKV GEMM via tf32 mma.sync + BN ----------------
// Y[nb][o][p] = sum_c W[o][c] * x[nb][c][p].
// Block: 64o x 128p, 128 threads = 4 warps (2x2), warp tile 32o x 64p.
// K chunked by 64. Compensated tf32 (Ah*Bh + Ah*Bl + Al*Bh).
// smem floats: xs_hi[64][136] @0, xs_lo @8704, ws_hi[64][72] @17408,
//              ws_lo @22016, sbn @26624, tbn @26688 ; total 26752 floats
#define QSM (26752 * 4)

__global__ __launch_bounds__(128) void qkv_kernel(
    const float* __restrict__ x,
    const float* __restrict__ qg, const float* __restrict__ qb,
    const float* __restrict__ qm, const float* __restrict__ qv) {
    extern __shared__ float qs[];
    float* xs_hi = qs;
    float* xs_lo = qs + 8704;
    float* ws_hi = qs + 17408;
    float* ws_lo = qs + 22016;
    float* sbn   = qs + 26624;
    float* tbn   = qs + 26688;

    int tid = threadIdx.x;
    int lane = tid & 31, wid = tid >> 5;
    int wm = wid >> 1, wn = wid & 1;          // warp grid 2x2
    int pt = blockIdx.x, ot = blockIdx.y, nb = blockIdx.z;
    const float* xp = x + (size_t)nb * (128 * 16384) + pt * 128;

    if (tid < 64) {
        int o = ot * 64 + tid;
        float s = qg[o] * rsqrtf(qv[o] + EPS);
        sbn[tid] = s;
        tbn[tid] = qb[o] - qm[o] * s;
    }

    float d[2][8][4];
#pragma unroll
    for (int m = 0; m < 2; m++)
#pragma unroll
        for (int n = 0; n < 8; n++)
#pragma unroll
            for (int r = 0; r < 4; r++) d[m][n][r] = 0.f;

    int row = lane >> 2, kq = lane & 3;

    for (int cc = 0; cc < 2; cc++) {
        // load + split x chunk: 64c x 128p
#pragma unroll
        for (int k = 0; k < 16; k++) {
            int f = tid + k * 128;
            int c = f >> 5, p4 = (f & 31) << 2;
            float4 v = *(const float4*)(xp + (size_t)(cc * 64 + c) * 16384 + p4);
            float4 h, l;
            h.x = __uint_as_float(to_tf32(v.x)); l.x = __uint_as_float(to_tf32(v.x - h.x));
            h.y = __uint_as_float(to_tf32(v.y)); l.y = __uint_as_float(to_tf32(v.y - h.y));
            h.z = __uint_as_float(to_tf32(v.z)); l.z = __uint_as_float(to_tf32(v.z - h.z));
            h.w = __uint_as_float(to_tf32(v.w)); l.w = __uint_as_float(to_tf32(v.w - h.w));
            *(float4*)&xs_hi[c * 136 + p4] = h;
            *(float4*)&xs_lo[c * 136 + p4] = l;
        }
        // load ws chunk (already split): 64c x 64o
#pragma unroll
        for (int k = 0; k < 8; k++) {
            int f = tid + k * 128;
            int c = f >> 4, o4 = (f & 15) << 2;
            *(float4*)&ws_hi[c * 72 + o4] =
                *(const float4*)(g_wt_hi + (cc * 64 + c) * 256 + ot * 64 + o4);
            *(float4*)&ws_lo[c * 72 + o4] =
                *(const float4*)(g_wt_lo + (cc * 64 + c) * 256 + ot * 64 + o4);
        }
        __syncthreads();

#pragma unroll
        for (int kc = 0; kc < 8; kc++) {
            int k0 = kc * 8 + kq;
            u32 ah[2][4], al[2][4];
#pragma unroll
            for (int m = 0; m < 2; m++) {
                int wo = wm * 32 + m * 16;
                ah[m][0] = __float_as_uint(ws_hi[k0 * 72 + wo + row]);
                ah[m][1] = __float_as_uint(ws_hi[k0 * 72 + wo + row + 8]);
                ah[m][2] = __float_as_uint(ws_hi[(k0 + 4) * 72 + wo + row]);
                ah[m][3] = __float_as_uint(ws_hi[(k0 + 4) * 72 + wo + row + 8]);
                al[m][0] = __float_as_uint(ws_lo[k0 * 72 + wo + row]);
                al[m][1] = __float_as_uint(ws_lo[k0 * 72 + wo + row + 8]);
                al[m][2] = __float_as_uint(ws_lo[(k0 + 4) * 72 + wo + row]);
                al[m][3] = __float_as_uint(ws_lo[(k0 + 4) * 72 + wo + row + 8]);
            }
#pragma unroll
            for (int n = 0; n < 8; n++) {
                int pc = wn * 64 + n * 8 + row;
                u32 bh[2], bl[2];
                bh[0] = __float_as_uint(xs_hi[k0 * 136 + pc]);
                bh[1] = __float_as_uint(xs_hi[(k0 + 4) * 136 + pc]);
                bl[0] = __float_as_uint(xs_lo[k0 * 136 + pc]);
                bl[1] = __float_as_uint(xs_lo[(k0 + 4) * 136 + pc]);
#pragma unroll
                for (int m = 0; m < 2; m++) {
                    mma_tf32(d[m][n], ah[m], bh);
                    mma_tf32(d[m][n], ah[m], bl);
                    mma_tf32(d[m][n], al[m], bh);
                }
            }
        }
        __syncthreads();
    }
    // BN epilogue + store (float2 per d-pair)
#pragma unroll
    for (int m = 0; m < 2; m++) {
        int lo0 = wm * 32 + m * 16 + row;      // local o, rows row / row+8
        float s0 = sbn[lo0],     t0 = tbn[lo0];
        float s1 = sbn[lo0 + 8], t1 = tbn[lo0 + 8];
        int o0 = ot * 64 + lo0;
#pragma unroll
        for (int n = 0; n < 8; n++) {
            int p = pt * 128 + wn * 64 + n * 8 + kq * 2;
            float2 r0, r1;
            r0.x = d[m][n][0] * s0 + t0; r0.y = d[m][n][1] * s0 + t0;
            r1.x = d[m][n][2] * s1 + t1; r1.y = d[m][n][3] * s1 + t1;
            *(float2*)(g_qkv + (size_t)(nb * 256 + o0) * 16384 + p) = r0;
            *(float2*)(g_qkv + (size_t)(nb * 256 + o0 + 8) * 16384 + p) = r1;
        }
    }
}

// ---------------- Kernel 2: attention per (n, g, 4-wide w tile) ----------------
// 256 threads: thread = (q = j-quarter, i in 0..63) owning rows {i, i+64}.
#define SMEM2 (31776 * 4)

__global__ __launch_bounds__(256) void attn_kernel(
    const float* __restrict__ simg, const float* __restrict__ simv,
    const float* __restrict__ og, const float* __restrict__ obt,
    const float* __restrict__ om, const float* __restrict__ ov,
    float* __restrict__ out) {
    extern __shared__ float sm2[];
    float* qkv_t  = sm2;
    float* ostage = sm2 + 16384;
    float* obuf   = sm2 + 24576;
    float* redm   = sm2 + 30720;
    float* reds   = sm2 + 31232;
    float* osc    = sm2 + 31744;
    float* osh    = sm2 + 31760;

    int tid = threadIdx.x;
    int w0 = blockIdx.x * 4;
    int g  = blockIdx.y;
    int n  = blockIdx.z;

    const float* src = g_qkv + (size_t)(n * 256 + g * 32) * 16384 + w0;
#pragma unroll
    for (int k = 0; k < 16; k++) {
        int f = tid + k * 256;
        int h = f & 127;
        int ch = f >> 7;
        float4 v4 = *(const float4*)(src + (size_t)ch * 16384 + h * 128);
        qkv_t[(0 * 32 + ch) * 128 + h] = v4.x;
        qkv_t[(1 * 32 + ch) * 128 + h] = v4.y;
        qkv_t[(2 * 32 + ch) * 128 + h] = v4.z;
        qkv_t[(3 * 32 + ch) * 128 + h] = v4.w;
    }
    if (tid < 16) {
        int co = g * 16 + tid;
        float s = og[co] * rsqrtf(ov[co] + EPS);
        osc[tid] = s;
        osh[tid] = obt[co] - om[co] * s;
    }
    float simscale = simg[g] * rsqrtf(simv[g] + EPS);
    __syncthreads();

    int q = tid >> 6;
    int i = tid & 63;
    int j0 = q * 32;

#pragma unroll 1
    for (int ww = 0; ww < 4; ww++) {
        const float* Q = qkv_t + ww * 32 * 128;
        u64 qd[2][8];
#pragma unroll
        for (int r = 0; r < 2; r++)
#pragma unroll
            for (int c = 0; c < 8; c++) {
                float v = Q[c * 128 + i + r * 64] * simscale;
                qd[r][c] = pack2(v, v);
            }
        f2u s2[2][16];
#pragma unroll
        for (int r = 0; r < 2; r++)
#pragma unroll
            for (int k = 0; k < 16; k++) s2[r][k].u = 0ull;
#pragma unroll
        for (int jj = 0; jj < 32; jj += 4) {
#pragma unroll
            for (int c = 0; c < 8; c++) {
                float4 k4 = *(const float4*)(Q + (8 + c) * 128 + j0 + jj);
                u64 kb0 = pack2(k4.x, k4.y);
                u64 kb1 = pack2(k4.z, k4.w);
                ffma2(s2[0][jj / 2].u,     qd[0][c], kb0);
                ffma2(s2[0][jj / 2 + 1].u, qd[0][c], kb1);
                ffma2(s2[1][jj / 2].u,     qd[1][c], kb0);
                ffma2(s2[1][jj / 2 + 1].u, qd[1][c], kb1);
            }
        }
        float mx0 = -1e30f, mx1 = -1e30f;
#pragma unroll
        for (int k = 0; k < 16; k++) {
            mx0 = fmaxf(mx0, fmaxf(s2[0][k].f.x, s2[0][k].f.y));
            mx1 = fmaxf(mx1, fmaxf(s2[1][k].f.x, s2[1][k].f.y));
        }
        redm[q * 128 + i] = mx0;
        redm[q * 128 + i + 64] = mx1;
        __syncthreads();
        mx0 = fmaxf(fmaxf(redm[i], redm[128 + i]),
                    fmaxf(redm[256 + i], redm[384 + i]));
        mx1 = fmaxf(fmaxf(redm[i + 64], redm[128 + i + 64]),
                    fmaxf(redm[256 + i + 64], redm[384 + i + 64]));
        float sum0 = 0.f, sum1 = 0.f;
#pragma unroll
        for (int k = 0; k < 16; k++) {
            float e0 = __expf(s2[0][k].f.x - mx0);
            float e1 = __expf(s2[0][k].f.y - mx0);
            s2[0][k].f.x = e0; s2[0][k].f.y = e1;
            sum0 += e0 + e1;
            float f0 = __expf(s2[1][k].f.x - mx1);
            float f1 = __expf(s2[1][k].f.y - mx1);
            s2[1][k].f.x = f0; s2[1][k].f.y = f1;
            sum1 += f0 + f1;
        }
        reds[q * 128 + i] = sum0;
        reds[q * 128 + i + 64] = sum1;
        __syncthreads();
        float inv0 = 1.f / (reds[i] + reds[128 + i] + reds[256 + i] + reds[384 + i]);
        float inv1 = 1.f / (reds[i + 64] + reds[128 + i + 64] +
                            reds[256 + i + 64] + reds[384 + i + 64]);
        f2u oc[2][16];
#pragma unroll
        for (int r = 0; r < 2; r++)
#pragma unroll
            for (int c = 0; c < 16; c++) oc[r][c].u = 0ull;
#pragma unroll
        for (int jj = 0; jj < 32; jj += 4) {
            u64 e00 = s2[0][jj / 2].u, e01 = s2[0][jj / 2 + 1].u;
            u64 e10 = s2[1][jj / 2].u, e11 = s2[1][jj / 2 + 1].u;
#pragma unroll
            for (int c = 0; c < 16; c++) {
                float4 v4 = *(const float4*)(Q + (16 + c) * 128 + j0 + jj);
                u64 vb0 = pack2(v4.x, v4.y);
                u64 vb1 = pack2(v4.z, v4.w);
                ffma2(oc[0][c].u, e00, vb0);
                ffma2(oc[0][c].u, e01, vb1);
                ffma2(oc[1][c].u, e10, vb0);
                ffma2(oc[1][c].u, e11, vb1);
            }
        }
        if (q) {
#pragma unroll
            for (int r = 0; r < 2; r++)
#pragma unroll
                for (int c = 0; c < 16; c++)
                    obuf[((q - 1) * 16 + c) * 128 + i + r * 64] =
                        oc[r][c].f.x + oc[r][c].f.y;
        }
        __syncthreads();
        if (!q) {
#pragma unroll
            for (int r = 0; r < 2; r++) {
                float inv = r ? inv1 : inv0;
                int rr = i + r * 64;
#pragma unroll
                for (int c = 0; c < 16; c++) {
                    float t = (oc[r][c].f.x + oc[r][c].f.y
                               + obuf[c * 128 + rr]
                               + obuf[(16 + c) * 128 + rr]
                               + obuf[(32 + c) * 128 + rr]) * inv;
                    ostage[(c * 128 + rr) * 4 + ww] = t * osc[c] + osh[c];
                }
            }
        }
        __syncthreads();
    }
    float* dst = out + (size_t)(n * 128 + g * 16) * 16384 + w0;
#pragma unroll
    for (int k = 0; k < 8; k++) {
        int f = tid + k * 256;
        int c = f >> 7, h = f & 127;
        float4 a = *(float4*)&ostage[(c * 128 + h) * 4];
        *(float4*)(dst + (size_t)c * 16384 + h * 128) = a;
    }
}

extern "C" void kernel_launch(void* const* d_in, const int* in_sizes, int n_in,
                              void* d_out, int out_size) {
    const float* x    = (const float*)d_in[0];
    const float* wq   = (const float*)d_in[1];
    const float* qg   = (const float*)d_in[2];
    const float* qb   = (const float*)d_in[3];
    const float* qm   = (const float*)d_in[4];
    const float* qv   = (const float*)d_in[5];
    const float* simg = (const float*)d_in[6];
    // d_in[7] sim_beta, d_in[8] sim_mean: shift cancels in softmax
    const float* simv = (const float*)d_in[9];
    const float* og   = (const float*)d_in[10];
    const float* obt  = (const float*)d_in[11];
    const float* om   = (const float*)d_in[12];
    const float* ov   = (const float*)d_in[13];
    float* out = (float*)d_out;

    cudaFuncSetAttribute(qkv_kernel,
                         cudaFuncAttributeMaxDynamicSharedMemorySize, QSM);
    cudaFuncSetAttribute(attn_kernel,
                         cudaFuncAttributeMaxDynamicSharedMemorySize, SMEM2);

    wt_kernel<<<128, 256>>>(wq);
    qkv_kernel<<<dim3(128, 4, 8), 128, QSM>>>(x, qg, qb, qm, qv);
    attn_kernel<<<dim3(32, 8, 8), 256, SMEM2>>>(simg, simv, og, obt, om, ov, out);
}